// round 3
// baseline (speedup 1.0000x reference)
#include <cuda_runtime.h>
#include <cuda_bf16.h>
#include <cstdint>

// SlotGNNLayer: B=8192, K=16, D=256, H=4, HD=64, E=8, EH=32
#define DD 256
#define NH 4
#define HDIM 64
#define KS 16
#define NE 8
#define EHID 32
#define NB 8192
#define NROWS (NB*KS)   // 131072

// Scratch (device globals: allocation-free per harness rules)
__device__ float g_q[NROWS*DD];
__device__ float g_k[NROWS*DD];
__device__ float g_v[NROWS*DD];
__device__ float g_att[NROWS*DD];

// ---------------------------------------------------------------- helpers
__device__ __forceinline__ unsigned f2tf(float f){
    unsigned u; asm("cvt.rna.tf32.f32 %0, %1;" : "=r"(u) : "f"(f)); return u;
}
__device__ __forceinline__ void cpa16(void* s, const void* g){
    unsigned a = (unsigned)__cvta_generic_to_shared(s);
    asm volatile("cp.async.ca.shared.global [%0], [%1], 16;" :: "r"(a), "l"(g));
}
__device__ __forceinline__ void cp_commit(){ asm volatile("cp.async.commit_group;"); }
template<int N> __device__ __forceinline__ void cp_wait(){
    asm volatile("cp.async.wait_group %0;" :: "n"(N));
}
__device__ __forceinline__ void mma8(float* c, const unsigned* a, const unsigned* b){
    asm volatile(
      "mma.sync.aligned.m16n8k8.row.col.f32.tf32.tf32.f32 "
      "{%0,%1,%2,%3},{%4,%5,%6,%7},{%8,%9},{%0,%1,%2,%3};"
      : "+f"(c[0]),"+f"(c[1]),"+f"(c[2]),"+f"(c[3])
      : "r"(a[0]),"r"(a[1]),"r"(a[2]),"r"(a[3]),"r"(b[0]),"r"(b[1]));
}

// ---------------------------------------------------------------- GEMM core
// C[M,256] tile (mtile: 128 rows, ntile: 128 cols) = A @ W (+bias)(+resid)
// A row-major [M,256], W row-major [256,256].
// tf32 mma.m16n8k8; 8 warps in 4x2 -> warp tile 32x64; BK=16, double-buffered cp.async.
__device__ __forceinline__ void gemm_core(
    const float* __restrict__ A, const float* __restrict__ W,
    const float* __restrict__ bias, const float* __restrict__ resid,
    float* __restrict__ C, int mtile, int ntile)
{
    __shared__ alignas(16) float As[2][128][20];   // pad 20: banks (4r+k)%32 distinct
    __shared__ alignas(16) float Bs[2][16][136];   // pad 136: banks (8k+n)%32 distinct
    const int tid = threadIdx.x;
    const float* Ab = A + (size_t)mtile * 128 * DD;
    const float* Wb = W + ntile * 128;

    // prefetch kt=0
    #pragma unroll
    for (int i=0;i<2;i++){ int id = tid + 256*i; int r = id>>2, c = id&3;
        cpa16(&As[0][r][c*4], Ab + (size_t)r*DD + c*4); }
    #pragma unroll
    for (int i=0;i<2;i++){ int id = tid + 256*i; int r = id>>5, c = id&31;
        cpa16(&Bs[0][r][c*4], Wb + (size_t)r*DD + c*4); }
    cp_commit();

    float acc[2][8][4];
    #pragma unroll
    for (int a=0;a<2;a++)
      #pragma unroll
      for (int b=0;b<8;b++)
        #pragma unroll
        for (int d=0;d<4;d++) acc[a][b][d]=0.f;

    const int wid = tid>>5, wm = wid>>1, wn = wid&1;
    const int lane = tid&31, g = lane>>2, tg = lane&3;

    for (int kt=0; kt<16; ++kt){
        if (kt < 15){
            const int buf = (kt+1)&1, k0 = (kt+1)*16;
            #pragma unroll
            for (int i=0;i<2;i++){ int id = tid + 256*i; int r = id>>2, c = id&3;
                cpa16(&As[buf][r][c*4], Ab + (size_t)r*DD + k0 + c*4); }
            #pragma unroll
            for (int i=0;i<2;i++){ int id = tid + 256*i; int r = id>>5, c = id&31;
                cpa16(&Bs[buf][r][c*4], Wb + (size_t)(k0+r)*DD + c*4); }
            cp_commit();
            cp_wait<1>();
        } else {
            cp_wait<0>();
        }
        __syncthreads();
        const int buf = kt&1;
        #pragma unroll
        for (int ks=0; ks<2; ++ks){
            unsigned afr[2][4], bfr[8][2];
            const int kk = ks*8 + tg;
            #pragma unroll
            for (int mt=0; mt<2; ++mt){
                int r = wm*32 + mt*16 + g;
                afr[mt][0] = f2tf(As[buf][r  ][kk  ]);
                afr[mt][1] = f2tf(As[buf][r+8][kk  ]);
                afr[mt][2] = f2tf(As[buf][r  ][kk+4]);
                afr[mt][3] = f2tf(As[buf][r+8][kk+4]);
            }
            #pragma unroll
            for (int nt=0; nt<8; ++nt){
                int n = wn*64 + nt*8 + g;
                bfr[nt][0] = f2tf(Bs[buf][kk  ][n]);
                bfr[nt][1] = f2tf(Bs[buf][kk+4][n]);
            }
            #pragma unroll
            for (int mt=0; mt<2; ++mt)
                #pragma unroll
                for (int nt=0; nt<8; ++nt)
                    mma8(acc[mt][nt], afr[mt], bfr[nt]);
        }
        __syncthreads();
    }

    // epilogue: +bias (+resid), float2 stores
    #pragma unroll
    for (int mt=0; mt<2; ++mt){
        #pragma unroll
        for (int nt=0; nt<8; ++nt){
            const int col = ntile*128 + wn*64 + nt*8 + tg*2;
            const float2 bb = *(const float2*)(bias + col);
            const size_t r0 = (size_t)(mtile*128 + wm*32 + mt*16 + g);
            const size_t r1 = r0 + 8;
            float2 v0 = make_float2(acc[mt][nt][0]+bb.x, acc[mt][nt][1]+bb.y);
            float2 v1 = make_float2(acc[mt][nt][2]+bb.x, acc[mt][nt][3]+bb.y);
            if (resid){
                float2 s0 = *(const float2*)(resid + r0*DD + col);
                float2 s1 = *(const float2*)(resid + r1*DD + col);
                v0.x += s0.x; v0.y += s0.y; v1.x += s1.x; v1.y += s1.y;
            }
            *(float2*)(C + r0*DD + col) = v0;
            *(float2*)(C + r1*DD + col) = v1;
        }
    }
}

// blockIdx.x in 0..5 selects {Q,K,V} x {ntile}; blockIdx.y = mtile.
// Consecutive blocks share the same A (slots) tile -> L2 reuse.
__global__ __launch_bounds__(256) void gemm_qkv_kernel(
    const float* __restrict__ slots,
    const float* __restrict__ Wq, const float* __restrict__ bq,
    const float* __restrict__ Wk, const float* __restrict__ bk,
    const float* __restrict__ Wv, const float* __restrict__ bv)
{
    const int sel = blockIdx.x;
    const int which = sel>>1, ntile = sel&1, mtile = blockIdx.y;
    const float* W = (which==0)?Wq:((which==1)?Wk:Wv);
    const float* b = (which==0)?bq:((which==1)?bk:bv);
    float* C = (which==0)?g_q:((which==1)?g_k:g_v);
    gemm_core(slots, W, b, nullptr, C, mtile, ntile);
}

__global__ __launch_bounds__(256) void gemm_o_kernel(
    const float* __restrict__ Wo, const float* __restrict__ bo,
    const float* __restrict__ slots, float* __restrict__ out)
{
    gemm_core(g_att, Wo, bo, slots, out, blockIdx.y, blockIdx.x);
}

// ---------------------------------------------------------------- attention
// One block per batch element. smem: Q (later V) + K, logits, edge-MLP weights.
__global__ __launch_bounds__(256) void attn_kernel(
    const float* __restrict__ edge,
    const float* __restrict__ We1, const float* __restrict__ be1,
    const float* __restrict__ We2, const float* __restrict__ be2)
{
    __shared__ alignas(16) float sA[16][260];  // Q, then reused for V
    __shared__ alignas(16) float sK[16][260];
    __shared__ alignas(16) float sL[NH*16*16]; // logits -> probabilities
    __shared__ alignas(16) float sW1[NE*EHID];
    __shared__ alignas(16) float sW2[EHID*NH];
    __shared__ float sB1[EHID];
    __shared__ float sB2[NH];

    const int tid = threadIdx.x;
    const size_t b = blockIdx.x;
    const size_t base = b * (KS*DD);   // 4096 floats per batch

    #pragma unroll
    for (int i=0;i<4;i++){
        int id = tid + 256*i;          // 1024 float4s per matrix
        int r = id>>6, c4 = id&63;
        *(float4*)&sA[r][c4*4] = *(const float4*)&g_q[base + (size_t)r*DD + c4*4];
        *(float4*)&sK[r][c4*4] = *(const float4*)&g_k[base + (size_t)r*DD + c4*4];
    }
    if (tid < 64) ((float4*)sW1)[tid] = ((const float4*)We1)[tid];
    if (tid < 32){ sB1[tid] = be1[tid]; ((float4*)sW2)[tid] = ((const float4*)We2)[tid]; }
    if (tid < 4)  sB2[tid] = be2[tid];
    __syncthreads();

    const int q = tid>>4, k = tid&15;

    // QK^T logits (scaled)
    #pragma unroll
    for (int h=0; h<NH; ++h){
        float acc = 0.f;
        #pragma unroll
        for (int dd=0; dd<16; ++dd){
            float4 qa = *(const float4*)&sA[q][h*HDIM + dd*4];
            float4 kb = *(const float4*)&sK[k][h*HDIM + dd*4];
            acc += qa.x*kb.x + qa.y*kb.y + qa.z*kb.z + qa.w*kb.w;
        }
        sL[h*256 + q*16 + k] = acc * 0.125f;  // 1/sqrt(64)
    }

    // edge MLP bias: relu(e @ We1 + be1) @ We2 + be2, added to logits
    {
        const float* ep = edge + ((b*KS + q)*KS + k)*NE;
        float e[8];
        *(float4*)&e[0] = *(const float4*)ep;
        *(float4*)&e[4] = *(const float4*)(ep+4);
        float oh[4] = {sB2[0], sB2[1], sB2[2], sB2[3]};
        #pragma unroll
        for (int j=0;j<EHID;++j){
            float hid = sB1[j];
            #pragma unroll
            for (int i=0;i<NE;++i) hid += e[i]*sW1[i*EHID + j];
            hid = fmaxf(hid, 0.f);
            #pragma unroll
            for (int h=0;h<NH;++h) oh[h] += hid * sW2[j*NH + h];
        }
        #pragma unroll
        for (int h=0;h<NH;++h) sL[h*256 + q*16 + k] += oh[h];
    }
    __syncthreads();

    // load V into sA (Q no longer needed) while threads<64 run softmax
    #pragma unroll
    for (int i=0;i<4;i++){
        int id = tid + 256*i;
        int r = id>>6, c4 = id&63;
        *(float4*)&sA[r][c4*4] = *(const float4*)&g_v[base + (size_t)r*DD + c4*4];
    }
    if (tid < 64){
        const int h = tid>>4, qq = tid&15;
        float* row = &sL[h*256 + qq*16];
        float m = row[0];
        #pragma unroll
        for (int kk=1; kk<16; ++kk) m = fmaxf(m, row[kk]);
        float ex[16]; float s = 0.f;
        #pragma unroll
        for (int kk=0; kk<16; ++kk){ ex[kk] = expf(row[kk]-m); s += ex[kk]; }
        const float inv = 1.f / s;
        #pragma unroll
        for (int kk=0; kk<16; ++kk) row[kk] = ex[kk]*inv;
    }
    __syncthreads();

    // out[q][d] = sum_k P[h(d)][q][k] * V[k][d]; thread (q,c) does d = c + 16*j
    {
        const int c = tid & 15;
        float outv[16];
        #pragma unroll
        for (int h=0; h<NH; ++h){
            float p[16];
            #pragma unroll
            for (int kk=0; kk<16; ++kk) p[kk] = sL[h*256 + q*16 + kk];
            #pragma unroll
            for (int j2=0; j2<4; ++j2){
                const int j = h*4 + j2;
                const int d = c + 16*j;
                float a = 0.f;
                #pragma unroll
                for (int kk=0; kk<16; ++kk) a += p[kk] * sA[kk][d];
                outv[j] = a;
            }
        }
        #pragma unroll
        for (int j=0;j<16;++j)
            g_att[base + (size_t)q*DD + c + 16*j] = outv[j];
    }
}

// ---------------------------------------------------------------- LayerNorm (in-place)
__global__ __launch_bounds__(256) void ln_kernel(
    float* __restrict__ x, const float* __restrict__ gamma, const float* __restrict__ beta)
{
    const int row  = blockIdx.x*8 + (threadIdx.x>>5);
    const int lane = threadIdx.x & 31;
    float* xr = x + (size_t)row*DD + lane*8;
    float4 v0 = *(float4*)xr;
    float4 v1 = *(float4*)(xr+4);
    float s  = v0.x+v0.y+v0.z+v0.w + v1.x+v1.y+v1.z+v1.w;
    float ss = v0.x*v0.x+v0.y*v0.y+v0.z*v0.z+v0.w*v0.w
             + v1.x*v1.x+v1.y*v1.y+v1.z*v1.z+v1.w*v1.w;
    #pragma unroll
    for (int o=16;o>0;o>>=1){
        s  += __shfl_xor_sync(0xffffffffu, s,  o);
        ss += __shfl_xor_sync(0xffffffffu, ss, o);
    }
    const float mean = s * (1.f/256.f);
    const float var  = ss * (1.f/256.f) - mean*mean;
    const float rstd = rsqrtf(var + 1e-5f);
    const float4 g0 = *(const float4*)&gamma[lane*8];
    const float4 g1 = *(const float4*)&gamma[lane*8+4];
    const float4 b0 = *(const float4*)&beta[lane*8];
    const float4 b1 = *(const float4*)&beta[lane*8+4];
    v0.x = (v0.x-mean)*rstd*g0.x + b0.x;
    v0.y = (v0.y-mean)*rstd*g0.y + b0.y;
    v0.z = (v0.z-mean)*rstd*g0.z + b0.z;
    v0.w = (v0.w-mean)*rstd*g0.w + b0.w;
    v1.x = (v1.x-mean)*rstd*g1.x + b1.x;
    v1.y = (v1.y-mean)*rstd*g1.y + b1.y;
    v1.z = (v1.z-mean)*rstd*g1.z + b1.z;
    v1.w = (v1.w-mean)*rstd*g1.w + b1.w;
    *(float4*)xr     = v0;
    *(float4*)(xr+4) = v1;
}

// ---------------------------------------------------------------- launch
extern "C" void kernel_launch(void* const* d_in, const int* in_sizes, int n_in,
                              void* d_out, int out_size)
{
    const float* slots = (const float*)d_in[0];
    const float* edge  = (const float*)d_in[1];
    const float* Wq  = (const float*)d_in[2];
    const float* bq  = (const float*)d_in[3];
    const float* Wk  = (const float*)d_in[4];
    const float* bk  = (const float*)d_in[5];
    const float* Wv  = (const float*)d_in[6];
    const float* bv  = (const float*)d_in[7];
    const float* We1 = (const float*)d_in[8];
    const float* be1 = (const float*)d_in[9];
    const float* We2 = (const float*)d_in[10];
    const float* be2 = (const float*)d_in[11];
    const float* Wo  = (const float*)d_in[12];
    const float* bo  = (const float*)d_in[13];
    const float* gamma = (const float*)d_in[14];
    const float* beta  = (const float*)d_in[15];
    float* out = (float*)d_out;

    gemm_qkv_kernel<<<dim3(6,1024), 256>>>(slots, Wq,bq, Wk,bk, Wv,bv);
    attn_kernel<<<NB, 256>>>(edge, We1, be1, We2, be2);
    gemm_o_kernel<<<dim3(2,1024), 256>>>(Wo, bo, slots, out);
    ln_kernel<<<NROWS/8, 256>>>(out, gamma, beta);
}

// round 11
// speedup vs baseline: 1.0334x; 1.0334x over previous
#include <cuda_runtime.h>
#include <cuda_fp16.h>
#include <cstdint>

// SlotGNNLayer: B=8192, K=16, D=256, H=4, HD=64, E=8, EH=32
#define DD 256
#define NH 4
#define HDIM 64
#define KS 16
#define NE 8
#define EHID 32
#define NB 8192
#define NROWS (NB*KS)   // 131072

// Scratch (device globals: allocation-free per harness rules)
__device__ __half g_slots_h[NROWS*DD];
__device__ __half g_qh[NROWS*DD];
__device__ __half g_kh[NROWS*DD];
__device__ __half g_vh[NROWS*DD];
__device__ __half g_atth[NROWS*DD];
__device__ __half g_wt_h[4*DD*DD];   // transposed Wq,Wk,Wv,Wo  ([N][K] each, half)

// ---------------------------------------------------------------- helpers
__device__ __forceinline__ void cpa16(void* s, const void* g){
    unsigned a = (unsigned)__cvta_generic_to_shared(s);
    asm volatile("cp.async.ca.shared.global [%0], [%1], 16;" :: "r"(a), "l"(g));
}
__device__ __forceinline__ void cp_commit(){ asm volatile("cp.async.commit_group;"); }
template<int N> __device__ __forceinline__ void cp_wait(){
    asm volatile("cp.async.wait_group %0;" :: "n"(N));
}
// fp16 mma: D(f32) += A(f16)[16x16] * B(f16)[16x8 col-major]
__device__ __forceinline__ void mma16(float* c, const unsigned* a, const unsigned* b){
    asm volatile(
      "mma.sync.aligned.m16n8k16.row.col.f32.f16.f16.f32 "
      "{%0,%1,%2,%3},{%4,%5,%6,%7},{%8,%9},{%0,%1,%2,%3};"
      : "+f"(c[0]),"+f"(c[1]),"+f"(c[2]),"+f"(c[3])
      : "r"(a[0]),"r"(a[1]),"r"(a[2]),"r"(a[3]),"r"(b[0]),"r"(b[1]));
}

// ---------------------------------------------------------------- converts
// slots fp32 -> half copy (8 elems/thread)
__global__ __launch_bounds__(256) void convert_slots_kernel(const float* __restrict__ src){
    size_t i = ((size_t)blockIdx.x*256 + threadIdx.x) * 8;
    float4 a = *(const float4*)(src + i);
    float4 b = *(const float4*)(src + i + 4);
    __half2* d = (__half2*)(g_slots_h + i);
    d[0] = __floats2half2_rn(a.x, a.y);
    d[1] = __floats2half2_rn(a.z, a.w);
    d[2] = __floats2half2_rn(b.x, b.y);
    d[3] = __floats2half2_rn(b.z, b.w);
}

// g_wt_h[m][n][k] = (half)W_m[k][n]
__global__ __launch_bounds__(256) void transpose_w_kernel(
    const float* __restrict__ Wq, const float* __restrict__ Wk,
    const float* __restrict__ Wv, const float* __restrict__ Wo)
{
    __shared__ float tile[32][33];
    const float* W = (blockIdx.z==0)?Wq:((blockIdx.z==1)?Wk:((blockIdx.z==2)?Wv:Wo));
    __half* T = g_wt_h + (size_t)blockIdx.z * DD * DD;
    const int lane = threadIdx.x & 31, grp = threadIdx.x >> 5;
    const int x = blockIdx.x*32 + lane;
    const int y0 = blockIdx.y*32;
    #pragma unroll
    for (int i=0;i<4;i++){
        int yl = grp*4 + i;
        tile[yl][lane] = W[(size_t)(y0+yl)*DD + x];
    }
    __syncthreads();
    const int ncol = blockIdx.y*32 + lane;
    const int nrow0 = blockIdx.x*32;
    #pragma unroll
    for (int i=0;i<4;i++){
        int xl = grp*4 + i;
        T[(size_t)(nrow0+xl)*DD + ncol] = __float2half_rn(tile[lane][xl]);
    }
}

// ---------------------------------------------------------------- fp16 GEMM core
// C tile [128 rows x 128 cols] = A[M,256](h) @ W(h, [N][K] transposed) (+bias)(+resid)
// 8 warps 4x2 -> warp tile 32x64; BK=16 (one m16n8k16 step), double-buffered cp.async.
__device__ __forceinline__ void gemm_core_h(
    const __half* __restrict__ A, const __half* __restrict__ Wt,
    const float* __restrict__ bias, const float* __restrict__ resid,
    float* __restrict__ Cf, __half* __restrict__ Ch, int mtile, int ntile)
{
    __shared__ __half As[2][128][16];   // 4KB/buf
    __shared__ __half Bs[2][128][16];   // [n][k]
    const int tid = threadIdx.x;
    const __half* Ab = A  + (size_t)mtile * 128 * DD;
    const __half* Wb = Wt + (size_t)ntile * 128 * DD;
    const int r2 = tid >> 1, c2 = tid & 1;   // 256 chunks of 16B per tile

    cpa16(&As[0][r2][c2*8], Ab + (size_t)r2*DD + c2*8);
    cpa16(&Bs[0][r2][c2*8], Wb + (size_t)r2*DD + c2*8);
    cp_commit();

    float acc[2][8][4];
    #pragma unroll
    for (int a=0;a<2;a++)
      #pragma unroll
      for (int b=0;b<8;b++)
        #pragma unroll
        for (int d=0;d<4;d++) acc[a][b][d]=0.f;

    const int wid = tid>>5, wm = wid>>1, wn = wid&1;
    const int lane = tid&31, g = lane>>2, tg = lane&3;

    for (int kt=0; kt<16; ++kt){
        if (kt < 15){
            const int buf = (kt+1)&1, k0 = (kt+1)*16;
            cpa16(&As[buf][r2][c2*8], Ab + (size_t)r2*DD + k0 + c2*8);
            cpa16(&Bs[buf][r2][c2*8], Wb + (size_t)r2*DD + k0 + c2*8);
            cp_commit();
            cp_wait<1>();
        } else {
            cp_wait<0>();
        }
        __syncthreads();
        const int buf = kt&1;
        unsigned afr[2][4], bfr[8][2];
        #pragma unroll
        for (int mt=0; mt<2; ++mt){
            const int row = wm*32 + mt*16 + g;
            afr[mt][0] = *(const unsigned*)&As[buf][row  ][2*tg  ];
            afr[mt][1] = *(const unsigned*)&As[buf][row+8][2*tg  ];
            afr[mt][2] = *(const unsigned*)&As[buf][row  ][2*tg+8];
            afr[mt][3] = *(const unsigned*)&As[buf][row+8][2*tg+8];
        }
        #pragma unroll
        for (int nt=0; nt<8; ++nt){
            const int n = wn*64 + nt*8 + g;
            bfr[nt][0] = *(const unsigned*)&Bs[buf][n][2*tg  ];
            bfr[nt][1] = *(const unsigned*)&Bs[buf][n][2*tg+8];
        }
        #pragma unroll
        for (int mt=0; mt<2; ++mt)
            #pragma unroll
            for (int nt=0; nt<8; ++nt)
                mma16(acc[mt][nt], afr[mt], bfr[nt]);
        __syncthreads();
    }

    // epilogue
    #pragma unroll
    for (int mt=0; mt<2; ++mt){
        #pragma unroll
        for (int nt=0; nt<8; ++nt){
            const int col = ntile*128 + wn*64 + nt*8 + tg*2;
            const float2 bb = *(const float2*)(bias + col);
            const size_t r0 = (size_t)(mtile*128 + wm*32 + mt*16 + g);
            const size_t r1 = r0 + 8;
            float2 v0 = make_float2(acc[mt][nt][0]+bb.x, acc[mt][nt][1]+bb.y);
            float2 v1 = make_float2(acc[mt][nt][2]+bb.x, acc[mt][nt][3]+bb.y);
            if (Ch){
                *(__half2*)(Ch + r0*DD + col) = __floats2half2_rn(v0.x, v0.y);
                *(__half2*)(Ch + r1*DD + col) = __floats2half2_rn(v1.x, v1.y);
            } else {
                float2 s0 = *(const float2*)(resid + r0*DD + col);
                float2 s1 = *(const float2*)(resid + r1*DD + col);
                v0.x += s0.x; v0.y += s0.y; v1.x += s1.x; v1.y += s1.y;
                *(float2*)(Cf + r0*DD + col) = v0;
                *(float2*)(Cf + r1*DD + col) = v1;
            }
        }
    }
}

// blockIdx.x: 6 combos {Q,K,V}x{ntile}; blockIdx.y = mtile (A-tile shared in L2)
__global__ __launch_bounds__(256) void gemm_qkv_h_kernel(
    const float* __restrict__ bq, const float* __restrict__ bk,
    const float* __restrict__ bv)
{
    const int sel = blockIdx.x;
    const int which = sel>>1, ntile = sel&1, mtile = blockIdx.y;
    const __half* Wt = g_wt_h + (size_t)which * DD * DD;
    const float* b   = (which==0)?bq:((which==1)?bk:bv);
    __half* C        = (which==0)?g_qh:((which==1)?g_kh:g_vh);
    gemm_core_h(g_slots_h, Wt, b, nullptr, nullptr, C, mtile, ntile);
}

__global__ __launch_bounds__(256) void gemm_o_h_kernel(
    const float* __restrict__ bo, const float* __restrict__ slots,
    float* __restrict__ out)
{
    gemm_core_h(g_atth, g_wt_h + (size_t)3*DD*DD, bo, slots, out, nullptr,
                blockIdx.y, blockIdx.x);
}

// ---------------------------------------------------------------- attention
// One block per batch element; Q/K/V in half globals, fp32 compute in smem/regs.
__global__ __launch_bounds__(256) void attn_kernel(
    const float* __restrict__ edge,
    const float* __restrict__ We1, const float* __restrict__ be1,
    const float* __restrict__ We2, const float* __restrict__ be2)
{
    __shared__ alignas(16) float sA[16][260];  // Q, then V, then out restage
    __shared__ alignas(16) float sK[16][260];
    __shared__ alignas(16) float sL[NH*16*16];
    __shared__ alignas(16) float sW1[NE*EHID];
    __shared__ alignas(16) float sW2[EHID*NH];
    __shared__ float sB1[EHID];
    __shared__ float sB2[NH];

    const int tid = threadIdx.x;
    const size_t b = blockIdx.x;
    const size_t base = b * (KS*DD);

    #pragma unroll
    for (int i=0;i<4;i++){
        int id = tid + 256*i;          // 1024 groups of 4 elems per matrix
        int r = id>>6, c4 = id&63;
        {
            const __half2* p = (const __half2*)(g_qh + base + (size_t)r*DD + c4*4);
            float2 f0 = __half22float2(p[0]), f1 = __half22float2(p[1]);
            sA[r][c4*4+0]=f0.x; sA[r][c4*4+1]=f0.y; sA[r][c4*4+2]=f1.x; sA[r][c4*4+3]=f1.y;
        }
        {
            const __half2* p = (const __half2*)(g_kh + base + (size_t)r*DD + c4*4);
            float2 f0 = __half22float2(p[0]), f1 = __half22float2(p[1]);
            sK[r][c4*4+0]=f0.x; sK[r][c4*4+1]=f0.y; sK[r][c4*4+2]=f1.x; sK[r][c4*4+3]=f1.y;
        }
    }
    if (tid < 64) ((float4*)sW1)[tid] = ((const float4*)We1)[tid];
    if (tid < 32){ sB1[tid] = be1[tid]; ((float4*)sW2)[tid] = ((const float4*)We2)[tid]; }
    if (tid < 4)  sB2[tid] = be2[tid];
    __syncthreads();

    const int q = tid>>4, k = tid&15;

    // QK^T logits (scaled)
    #pragma unroll
    for (int h=0; h<NH; ++h){
        float acc = 0.f;
        #pragma unroll
        for (int dd=0; dd<16; ++dd){
            float4 qa = *(const float4*)&sA[q][h*HDIM + dd*4];
            float4 kb = *(const float4*)&sK[k][h*HDIM + dd*4];
            acc += qa.x*kb.x + qa.y*kb.y + qa.z*kb.z + qa.w*kb.w;
        }
        sL[h*256 + q*16 + k] = acc * 0.125f;
    }

    // edge MLP bias
    {
        const float* ep = edge + ((b*KS + q)*KS + k)*NE;
        float e[8];
        *(float4*)&e[0] = *(const float4*)ep;
        *(float4*)&e[4] = *(const float4*)(ep+4);
        float oh[4] = {sB2[0], sB2[1], sB2[2], sB2[3]};
        #pragma unroll
        for (int j=0;j<EHID;++j){
            float hid = sB1[j];
            #pragma unroll
            for (int i=0;i<NE;++i) hid += e[i]*sW1[i*EHID + j];
            hid = fmaxf(hid, 0.f);
            #pragma unroll
            for (int h=0;h<NH;++h) oh[h] += hid * sW2[j*NH + h];
        }
        #pragma unroll
        for (int h=0;h<NH;++h) sL[h*256 + q*16 + k] += oh[h];
    }
    __syncthreads();

    // load V into sA; softmax on threads<64
    #pragma unroll
    for (int i=0;i<4;i++){
        int id = tid + 256*i;
        int r = id>>6, c4 = id&63;
        const __half2* p = (const __half2*)(g_vh + base + (size_t)r*DD + c4*4);
        float2 f0 = __half22float2(p[0]), f1 = __half22float2(p[1]);
        sA[r][c4*4+0]=f0.x; sA[r][c4*4+1]=f0.y; sA[r][c4*4+2]=f1.x; sA[r][c4*4+3]=f1.y;
    }
    if (tid < 64){
        const int h = tid>>4, qq = tid&15;
        float* row = &sL[h*256 + qq*16];
        float m = row[0];
        #pragma unroll
        for (int kk=1; kk<16; ++kk) m = fmaxf(m, row[kk]);
        float ex[16]; float s = 0.f;
        #pragma unroll
        for (int kk=0; kk<16; ++kk){ ex[kk] = expf(row[kk]-m); s += ex[kk]; }
        const float inv = 1.f / s;
        #pragma unroll
        for (int kk=0; kk<16; ++kk) row[kk] = ex[kk]*inv;
    }
    __syncthreads();

    // out[q][d] = sum_k P[h(d)][q][k] * V[k][d]
    const int c = tid & 15;
    float outv[16];
    #pragma unroll
    for (int h=0; h<NH; ++h){
        float p[16];
        #pragma unroll
        for (int kk=0; kk<16; ++kk) p[kk] = sL[h*256 + q*16 + kk];
        #pragma unroll
        for (int j2=0; j2<4; ++j2){
            const int j = h*4 + j2;
            const int d = c + 16*j;
            float a = 0.f;
            #pragma unroll
            for (int kk=0; kk<16; ++kk) a += p[kk] * sA[kk][d];
            outv[j] = a;
        }
    }
    __syncthreads();                       // all V reads done
    #pragma unroll
    for (int j=0;j<16;++j) sA[q][c + 16*j] = outv[j];
    __syncthreads();
    // coalesced half store: thread t -> row t>>4, cols (t&15)*16..+15 (32B)
    {
        const int r = tid>>4, c0 = (tid&15)*16;
        __half2 h[8];
        #pragma unroll
        for (int j=0;j<8;++j)
            h[j] = __floats2half2_rn(sA[r][c0+2*j], sA[r][c0+2*j+1]);
        *(uint4*)(g_atth + base + (size_t)r*DD + c0)     = *(uint4*)&h[0];
        *(uint4*)(g_atth + base + (size_t)r*DD + c0 + 8) = *(uint4*)&h[4];
    }
}

// ---------------------------------------------------------------- LayerNorm (in-place)
__global__ __launch_bounds__(256) void ln_kernel(
    float* __restrict__ x, const float* __restrict__ gamma, const float* __restrict__ beta)
{
    const int row  = blockIdx.x*8 + (threadIdx.x>>5);
    const int lane = threadIdx.x & 31;
    float* xr = x + (size_t)row*DD + lane*8;
    float4 v0 = *(float4*)xr;
    float4 v1 = *(float4*)(xr+4);
    float s  = v0.x+v0.y+v0.z+v0.w + v1.x+v1.y+v1.z+v1.w;
    float ss = v0.x*v0.x+v0.y*v0.y+v0.z*v0.z+v0.w*v0.w
             + v1.x*v1.x+v1.y*v1.y+v1.z*v1.z+v1.w*v1.w;
    #pragma unroll
    for (int o=16;o>0;o>>=1){
        s  += __shfl_xor_sync(0xffffffffu, s,  o);
        ss += __shfl_xor_sync(0xffffffffu, ss, o);
    }
    const float mean = s * (1.f/256.f);
    const float var  = ss * (1.f/256.f) - mean*mean;
    const float rstd = rsqrtf(var + 1e-5f);
    const float4 g0 = *(const float4*)&gamma[lane*8];
    const float4 g1 = *(const float4*)&gamma[lane*8+4];
    const float4 b0 = *(const float4*)&beta[lane*8];
    const float4 b1 = *(const float4*)&beta[lane*8+4];
    v0.x = (v0.x-mean)*rstd*g0.x + b0.x;
    v0.y = (v0.y-mean)*rstd*g0.y + b0.y;
    v0.z = (v0.z-mean)*rstd*g0.z + b0.z;
    v0.w = (v0.w-mean)*rstd*g0.w + b0.w;
    v1.x = (v1.x-mean)*rstd*g1.x + b1.x;
    v1.y = (v1.y-mean)*rstd*g1.y + b1.y;
    v1.z = (v1.z-mean)*rstd*g1.z + b1.z;
    v1.w = (v1.w-mean)*rstd*g1.w + b1.w;
    *(float4*)xr     = v0;
    *(float4*)(xr+4) = v1;
}

// ---------------------------------------------------------------- launch
extern "C" void kernel_launch(void* const* d_in, const int* in_sizes, int n_in,
                              void* d_out, int out_size)
{
    const float* slots = (const float*)d_in[0];
    const float* edge  = (const float*)d_in[1];
    const float* Wq  = (const float*)d_in[2];
    const float* bq  = (const float*)d_in[3];
    const float* Wk  = (const float*)d_in[4];
    const float* bk  = (const float*)d_in[5];
    const float* Wv  = (const float*)d_in[6];
    const float* bv  = (const float*)d_in[7];
    const float* We1 = (const float*)d_in[8];
    const float* be1 = (const float*)d_in[9];
    const float* We2 = (const float*)d_in[10];
    const float* be2 = (const float*)d_in[11];
    const float* Wo  = (const float*)d_in[12];
    const float* bo  = (const float*)d_in[13];
    const float* gamma = (const float*)d_in[14];
    const float* beta  = (const float*)d_in[15];
    float* out = (float*)d_out;

    convert_slots_kernel<<<NROWS*DD/(256*8), 256>>>(slots);
    transpose_w_kernel<<<dim3(8,8,4), 256>>>(Wq, Wk, Wv, Wo);
    gemm_qkv_h_kernel<<<dim3(6,1024), 256>>>(bq, bk, bv);
    attn_kernel<<<NB, 256>>>(edge, We1, be1, We2, be2);
    gemm_o_h_kernel<<<dim3(2,1024), 256>>>(bo, slots, out);
    ln_kernel<<<NROWS/8, 256>>>(out, gamma, beta);
}

// round 14
// speedup vs baseline: 1.1334x; 1.0968x over previous
#include <cuda_runtime.h>
#include <cuda_fp16.h>
#include <cstdint>

// SlotGNNLayer: B=8192, K=16, D=256, H=4, HD=64, E=8, EH=32
#define DD 256
#define NH 4
#define HDIM 64
#define KS 16
#define NE 8
#define EHID 32
#define NB 8192
#define NROWS (NB*KS)   // 131072
#define SHH 260         // halves per smem row (520B, 8B-aligned rows, conflict-free stride)

// Scratch (device globals: allocation-free per harness rules)
__device__ __half g_slots_h[NROWS*DD];
__device__ __half g_qh[NROWS*DD];
__device__ __half g_kh[NROWS*DD];
__device__ __half g_vh[NROWS*DD];
__device__ __half g_atth[NROWS*DD];
__device__ __half g_wt_h[4*DD*DD];   // transposed Wq,Wk,Wv,Wo  ([N][K] each, half)

// ---------------------------------------------------------------- helpers
__device__ __forceinline__ void cpa16(void* s, const void* g){
    unsigned a = (unsigned)__cvta_generic_to_shared(s);
    asm volatile("cp.async.ca.shared.global [%0], [%1], 16;" :: "r"(a), "l"(g));
}
__device__ __forceinline__ void cp_commit(){ asm volatile("cp.async.commit_group;"); }
template<int N> __device__ __forceinline__ void cp_wait(){
    asm volatile("cp.async.wait_group %0;" :: "n"(N));
}
// fp16 mma: D(f32) += A(f16)[16x16] * B(f16)[16x8 col-major]
__device__ __forceinline__ void mma16(float* c, const unsigned* a, const unsigned* b){
    asm volatile(
      "mma.sync.aligned.m16n8k16.row.col.f32.f16.f16.f32 "
      "{%0,%1,%2,%3},{%4,%5,%6,%7},{%8,%9},{%0,%1,%2,%3};"
      : "+f"(c[0]),"+f"(c[1]),"+f"(c[2]),"+f"(c[3])
      : "r"(a[0]),"r"(a[1]),"r"(a[2]),"r"(a[3]),"r"(b[0]),"r"(b[1]));
}

// ---------------------------------------------------------------- converts
__global__ __launch_bounds__(256) void convert_slots_kernel(const float* __restrict__ src){
    size_t i = ((size_t)blockIdx.x*256 + threadIdx.x) * 8;
    float4 a = *(const float4*)(src + i);
    float4 b = *(const float4*)(src + i + 4);
    __half2* d = (__half2*)(g_slots_h + i);
    d[0] = __floats2half2_rn(a.x, a.y);
    d[1] = __floats2half2_rn(a.z, a.w);
    d[2] = __floats2half2_rn(b.x, b.y);
    d[3] = __floats2half2_rn(b.z, b.w);
}

// g_wt_h[m][n][k] = (half)W_m[k][n]
__global__ __launch_bounds__(256) void transpose_w_kernel(
    const float* __restrict__ Wq, const float* __restrict__ Wk,
    const float* __restrict__ Wv, const float* __restrict__ Wo)
{
    __shared__ float tile[32][33];
    const float* W = (blockIdx.z==0)?Wq:((blockIdx.z==1)?Wk:((blockIdx.z==2)?Wv:Wo));
    __half* T = g_wt_h + (size_t)blockIdx.z * DD * DD;
    const int lane = threadIdx.x & 31, grp = threadIdx.x >> 5;
    const int x = blockIdx.x*32 + lane;
    const int y0 = blockIdx.y*32;
    #pragma unroll
    for (int i=0;i<4;i++){
        int yl = grp*4 + i;
        tile[yl][lane] = W[(size_t)(y0+yl)*DD + x];
    }
    __syncthreads();
    const int ncol = blockIdx.y*32 + lane;
    const int nrow0 = blockIdx.x*32;
    #pragma unroll
    for (int i=0;i<4;i++){
        int xl = grp*4 + i;
        T[(size_t)(nrow0+xl)*DD + ncol] = __float2half_rn(tile[lane][xl]);
    }
}

// ---------------------------------------------------------------- fp16 GEMM core
__device__ __forceinline__ void gemm_core_h(
    const __half* __restrict__ A, const __half* __restrict__ Wt,
    const float* __restrict__ bias, const float* __restrict__ resid,
    float* __restrict__ Cf, __half* __restrict__ Ch, int mtile, int ntile)
{
    __shared__ __half As[2][128][16];
    __shared__ __half Bs[2][128][16];   // [n][k]
    const int tid = threadIdx.x;
    const __half* Ab = A  + (size_t)mtile * 128 * DD;
    const __half* Wb = Wt + (size_t)ntile * 128 * DD;
    const int r2 = tid >> 1, c2 = tid & 1;

    cpa16(&As[0][r2][c2*8], Ab + (size_t)r2*DD + c2*8);
    cpa16(&Bs[0][r2][c2*8], Wb + (size_t)r2*DD + c2*8);
    cp_commit();

    float acc[2][8][4];
    #pragma unroll
    for (int a=0;a<2;a++)
      #pragma unroll
      for (int b=0;b<8;b++)
        #pragma unroll
        for (int d=0;d<4;d++) acc[a][b][d]=0.f;

    const int wid = tid>>5, wm = wid>>1, wn = wid&1;
    const int lane = tid&31, g = lane>>2, tg = lane&3;

    for (int kt=0; kt<16; ++kt){
        if (kt < 15){
            const int buf = (kt+1)&1, k0 = (kt+1)*16;
            cpa16(&As[buf][r2][c2*8], Ab + (size_t)r2*DD + k0 + c2*8);
            cpa16(&Bs[buf][r2][c2*8], Wb + (size_t)r2*DD + k0 + c2*8);
            cp_commit();
            cp_wait<1>();
        } else {
            cp_wait<0>();
        }
        __syncthreads();
        const int buf = kt&1;
        unsigned afr[2][4], bfr[8][2];
        #pragma unroll
        for (int mt=0; mt<2; ++mt){
            const int row = wm*32 + mt*16 + g;
            afr[mt][0] = *(const unsigned*)&As[buf][row  ][2*tg  ];
            afr[mt][1] = *(const unsigned*)&As[buf][row+8][2*tg  ];
            afr[mt][2] = *(const unsigned*)&As[buf][row  ][2*tg+8];
            afr[mt][3] = *(const unsigned*)&As[buf][row+8][2*tg+8];
        }
        #pragma unroll
        for (int nt=0; nt<8; ++nt){
            const int n = wn*64 + nt*8 + g;
            bfr[nt][0] = *(const unsigned*)&Bs[buf][n][2*tg  ];
            bfr[nt][1] = *(const unsigned*)&Bs[buf][n][2*tg+8];
        }
        #pragma unroll
        for (int mt=0; mt<2; ++mt)
            #pragma unroll
            for (int nt=0; nt<8; ++nt)
                mma16(acc[mt][nt], afr[mt], bfr[nt]);
        __syncthreads();
    }

    #pragma unroll
    for (int mt=0; mt<2; ++mt){
        #pragma unroll
        for (int nt=0; nt<8; ++nt){
            const int col = ntile*128 + wn*64 + nt*8 + tg*2;
            const float2 bb = *(const float2*)(bias + col);
            const size_t r0 = (size_t)(mtile*128 + wm*32 + mt*16 + g);
            const size_t r1 = r0 + 8;
            float2 v0 = make_float2(acc[mt][nt][0]+bb.x, acc[mt][nt][1]+bb.y);
            float2 v1 = make_float2(acc[mt][nt][2]+bb.x, acc[mt][nt][3]+bb.y);
            if (Ch){
                *(__half2*)(Ch + r0*DD + col) = __floats2half2_rn(v0.x, v0.y);
                *(__half2*)(Ch + r1*DD + col) = __floats2half2_rn(v1.x, v1.y);
            } else {
                float2 s0 = *(const float2*)(resid + r0*DD + col);
                float2 s1 = *(const float2*)(resid + r1*DD + col);
                v0.x += s0.x; v0.y += s0.y; v1.x += s1.x; v1.y += s1.y;
                *(float2*)(Cf + r0*DD + col) = v0;
                *(float2*)(Cf + r1*DD + col) = v1;
            }
        }
    }
}

__global__ __launch_bounds__(256) void gemm_qkv_h_kernel(
    const float* __restrict__ bq, const float* __restrict__ bk,
    const float* __restrict__ bv)
{
    const int sel = blockIdx.x;
    const int which = sel>>1, ntile = sel&1, mtile = blockIdx.y;
    const __half* Wt = g_wt_h + (size_t)which * DD * DD;
    const float* b   = (which==0)?bq:((which==1)?bk:bv);
    __half* C        = (which==0)?g_qh:((which==1)?g_kh:g_vh);
    gemm_core_h(g_slots_h, Wt, b, nullptr, nullptr, C, mtile, ntile);
}

__global__ __launch_bounds__(256) void gemm_o_h_kernel(
    const float* __restrict__ bo, const float* __restrict__ slots,
    float* __restrict__ out)
{
    gemm_core_h(g_atth, g_wt_h + (size_t)3*DD*DD, bo, slots, out, nullptr,
                blockIdx.y, blockIdx.x);
}

// ---------------------------------------------------------------- attention (v2: half smem, conflict-free)
// One block per batch; Q/K/V staged in smem as half (row stride 260 halves = 520B).
// Word-stride 130 == 2 (mod 32) -> 16 row-readers hit distinct banks. fp32 compute.
__global__ __launch_bounds__(256) void attn_kernel(
    const float* __restrict__ edge,
    const float* __restrict__ We1, const float* __restrict__ be1,
    const float* __restrict__ We2, const float* __restrict__ be2)
{
    __shared__ alignas(16) __half sQ[16*SHH];   // Q; reused as half out restage
    __shared__ alignas(16) __half sKh[16*SHH];
    __shared__ alignas(16) __half sV[16*SHH];
    __shared__ alignas(16) float sL[NH*16*16];
    __shared__ alignas(16) float sW1[NE*EHID];
    __shared__ alignas(16) float sW2[EHID*NH];
    __shared__ float sB1[EHID];
    __shared__ float sB2[NH];

    const int tid = threadIdx.x;
    const size_t b = blockIdx.x;
    const size_t base = b * (KS*DD);

    // load Q,K,V (512 chunks of 8 halves each matrix); smem rows 8B-aligned -> uint2 stores
    #pragma unroll
    for (int i=0;i<2;i++){
        int id = tid + 256*i;
        int r = id>>5, c8 = id&31;
        size_t goff = base + (size_t)r*DD + c8*8;
        uint4 vq = *(const uint4*)(g_qh + goff);
        uint4 vk = *(const uint4*)(g_kh + goff);
        uint4 vv = *(const uint4*)(g_vh + goff);
        uint2* dq = (uint2*)((char*)sQ  + r*520 + c8*16);
        uint2* dk = (uint2*)((char*)sKh + r*520 + c8*16);
        uint2* dv = (uint2*)((char*)sV  + r*520 + c8*16);
        dq[0] = make_uint2(vq.x, vq.y); dq[1] = make_uint2(vq.z, vq.w);
        dk[0] = make_uint2(vk.x, vk.y); dk[1] = make_uint2(vk.z, vk.w);
        dv[0] = make_uint2(vv.x, vv.y); dv[1] = make_uint2(vv.z, vv.w);
    }
    if (tid < 64) ((float4*)sW1)[tid] = ((const float4*)We1)[tid];
    if (tid < 32){ sB1[tid] = be1[tid]; ((float4*)sW2)[tid] = ((const float4*)We2)[tid]; }
    if (tid < 4)  sB2[tid] = be2[tid];
    __syncthreads();

    const int q = tid>>4, k = tid&15;

    // QK^T logits: Q reads broadcast; K reads banks (2k+c)%32 all-distinct
    #pragma unroll
    for (int h=0; h<NH; ++h){
        const uint2* qp = (const uint2*)((char*)sQ  + q*520 + h*128);
        const uint2* kp = (const uint2*)((char*)sKh + k*520 + h*128);
        float acc = 0.f;
        #pragma unroll
        for (int i=0;i<16;i++){
            uint2 ua = qp[i], ub = kp[i];
            float2 a0 = __half22float2(*(__half2*)&ua.x);
            float2 a1 = __half22float2(*(__half2*)&ua.y);
            float2 b0 = __half22float2(*(__half2*)&ub.x);
            float2 b1 = __half22float2(*(__half2*)&ub.y);
            acc += a0.x*b0.x + a0.y*b0.y + a1.x*b1.x + a1.y*b1.y;
        }
        sL[h*256 + q*16 + k] = acc * 0.125f;
    }

    // edge MLP bias (unchanged, fp32 from global)
    {
        const float* ep = edge + ((b*KS + q)*KS + k)*NE;
        float e[8];
        *(float4*)&e[0] = *(const float4*)ep;
        *(float4*)&e[4] = *(const float4*)(ep+4);
        float oh[4] = {sB2[0], sB2[1], sB2[2], sB2[3]};
        #pragma unroll
        for (int j=0;j<EHID;++j){
            float hid = sB1[j];
            #pragma unroll
            for (int i=0;i<NE;++i) hid += e[i]*sW1[i*EHID + j];
            hid = fmaxf(hid, 0.f);
            #pragma unroll
            for (int h=0;h<NH;++h) oh[h] += hid * sW2[j*NH + h];
        }
        #pragma unroll
        for (int h=0;h<NH;++h) sL[h*256 + q*16 + k] += oh[h];
    }
    __syncthreads();

    // softmax on threads<64
    if (tid < 64){
        const int h = tid>>4, qq = tid&15;
        float* row = &sL[h*256 + qq*16];
        float m = row[0];
        #pragma unroll
        for (int kk=1; kk<16; ++kk) m = fmaxf(m, row[kk]);
        float ex[16]; float s = 0.f;
        #pragma unroll
        for (int kk=0; kk<16; ++kk){ ex[kk] = expf(row[kk]-m); s += ex[kk]; }
        const float inv = 1.f / s;
        #pragma unroll
        for (int kk=0; kk<16; ++kk) row[kk] = ex[kk]*inv;
    }
    __syncthreads();

    // PV: thread (q,c) owns dims d = h*64 + 4c + {0..3}; V loads conflict-free uint2
    const int c = tid & 15;
    float outv[NH][4];
    #pragma unroll
    for (int h=0; h<NH; ++h){
        float p[16];
        #pragma unroll
        for (int kk=0; kk<16; ++kk) p[kk] = sL[h*256 + q*16 + kk];
        float a0=0.f, a1=0.f, a2=0.f, a3=0.f;
        #pragma unroll
        for (int kk=0; kk<16; ++kk){
            uint2 uv = *(const uint2*)((char*)sV + kk*520 + (h*64 + 4*c)*2);
            float2 v01 = __half22float2(*(__half2*)&uv.x);
            float2 v23 = __half22float2(*(__half2*)&uv.y);
            a0 += p[kk]*v01.x; a1 += p[kk]*v01.y;
            a2 += p[kk]*v23.x; a3 += p[kk]*v23.y;
        }
        outv[h][0]=a0; outv[h][1]=a1; outv[h][2]=a2; outv[h][3]=a3;
    }
    // restage to sQ as half (sQ reads finished in QK phase, before earlier barrier)
    #pragma unroll
    for (int h=0; h<NH; ++h){
        __half2 h01 = __floats2half2_rn(outv[h][0], outv[h][1]);
        __half2 h23 = __floats2half2_rn(outv[h][2], outv[h][3]);
        *(uint2*)((char*)sQ + q*520 + (h*64 + 4*c)*2) =
            make_uint2(*(unsigned*)&h01, *(unsigned*)&h23);
    }
    __syncthreads();
    // coalesced store: thread t -> row t>>4, halves (t&15)*16..+15 (32B)
    {
        const int r = tid>>4, c0 = tid&15;
        const uint2* sp = (const uint2*)((char*)sQ + r*520 + c0*32);
        uint2 w0=sp[0], w1=sp[1], w2=sp[2], w3=sp[3];
        uint4 o0 = make_uint4(w0.x, w0.y, w1.x, w1.y);
        uint4 o1 = make_uint4(w2.x, w2.y, w3.x, w3.y);
        *(uint4*)(g_atth + base + (size_t)r*DD + c0*16)     = o0;
        *(uint4*)(g_atth + base + (size_t)r*DD + c0*16 + 8) = o1;
    }
}

// ---------------------------------------------------------------- LayerNorm (in-place)
__global__ __launch_bounds__(256) void ln_kernel(
    float* __restrict__ x, const float* __restrict__ gamma, const float* __restrict__ beta)
{
    const int row  = blockIdx.x*8 + (threadIdx.x>>5);
    const int lane = threadIdx.x & 31;
    float* xr = x + (size_t)row*DD + lane*8;
    float4 v0 = *(float4*)xr;
    float4 v1 = *(float4*)(xr+4);
    float s  = v0.x+v0.y+v0.z+v0.w + v1.x+v1.y+v1.z+v1.w;
    float ss = v0.x*v0.x+v0.y*v0.y+v0.z*v0.z+v0.w*v0.w
             + v1.x*v1.x+v1.y*v1.y+v1.z*v1.z+v1.w*v1.w;
    #pragma unroll
    for (int o=16;o>0;o>>=1){
        s  += __shfl_xor_sync(0xffffffffu, s,  o);
        ss += __shfl_xor_sync(0xffffffffu, ss, o);
    }
    const float mean = s * (1.f/256.f);
    const float var  = ss * (1.f/256.f) - mean*mean;
    const float rstd = rsqrtf(var + 1e-5f);
    const float4 g0 = *(const float4*)&gamma[lane*8];
    const float4 g1 = *(const float4*)&gamma[lane*8+4];
    const float4 b0 = *(const float4*)&beta[lane*8];
    const float4 b1 = *(const float4*)&beta[lane*8+4];
    v0.x = (v0.x-mean)*rstd*g0.x + b0.x;
    v0.y = (v0.y-mean)*rstd*g0.y + b0.y;
    v0.z = (v0.z-mean)*rstd*g0.z + b0.z;
    v0.w = (v0.w-mean)*rstd*g0.w + b0.w;
    v1.x = (v1.x-mean)*rstd*g1.x + b1.x;
    v1.y = (v1.y-mean)*rstd*g1.y + b1.y;
    v1.z = (v1.z-mean)*rstd*g1.z + b1.z;
    v1.w = (v1.w-mean)*rstd*g1.w + b1.w;
    *(float4*)xr     = v0;
    *(float4*)(xr+4) = v1;
}

// ---------------------------------------------------------------- launch
extern "C" void kernel_launch(void* const* d_in, const int* in_sizes, int n_in,
                              void* d_out, int out_size)
{
    const float* slots = (const float*)d_in[0];
    const float* edge  = (const float*)d_in[1];
    const float* Wq  = (const float*)d_in[2];
    const float* bq  = (const float*)d_in[3];
    const float* Wk  = (const float*)d_in[4];
    const float* bk  = (const float*)d_in[5];
    const float* Wv  = (const float*)d_in[6];
    const float* bv  = (const float*)d_in[7];
    const float* We1 = (const float*)d_in[8];
    const float* be1 = (const float*)d_in[9];
    const float* We2 = (const float*)d_in[10];
    const float* be2 = (const float*)d_in[11];
    const float* Wo  = (const float*)d_in[12];
    const float* bo  = (const float*)d_in[13];
    const float* gamma = (const float*)d_in[14];
    const float* beta  = (const float*)d_in[15];
    float* out = (float*)d_out;

    convert_slots_kernel<<<NROWS*DD/(256*8), 256>>>(slots);
    transpose_w_kernel<<<dim3(8,8,4), 256>>>(Wq, Wk, Wv, Wo);
    gemm_qkv_h_kernel<<<dim3(6,1024), 256>>>(bq, bk, bv);
    attn_kernel<<<NB, 256>>>(edge, We1, be1, We2, be2);
    gemm_o_h_kernel<<<dim3(2,1024), 256>>>(bo, slots, out);
    ln_kernel<<<NROWS/8, 256>>>(out, gamma, beta);
}

// round 17
// speedup vs baseline: 1.1974x; 1.0565x over previous
#include <cuda_runtime.h>
#include <cuda_fp16.h>
#include <cstdint>

// SlotGNNLayer: B=8192, K=16, D=256, H=4, HD=64, E=8, EH=32
#define DD 256
#define NH 4
#define HDIM 64
#define KS 16
#define NE 8
#define EHID 32
#define NB 8192
#define NROWS (NB*KS)   // 131072
#define SHH 260         // halves per smem row (520B, 8B-aligned rows, conflict-free stride)

// Scratch (device globals: allocation-free per harness rules)
__device__ __half g_slots_h[NROWS*DD];
__device__ __half g_qh[NROWS*DD];
__device__ __half g_kh[NROWS*DD];
__device__ __half g_vh[NROWS*DD];
__device__ __half g_atth[NROWS*DD];
__device__ __half g_wt_h[4*DD*DD];   // transposed Wq,Wk,Wv,Wo  ([N][K] each, half)

// ---------------------------------------------------------------- helpers
__device__ __forceinline__ void cpa16(void* s, const void* g){
    unsigned a = (unsigned)__cvta_generic_to_shared(s);
    asm volatile("cp.async.ca.shared.global [%0], [%1], 16;" :: "r"(a), "l"(g));
}
__device__ __forceinline__ void cp_commit(){ asm volatile("cp.async.commit_group;"); }
template<int N> __device__ __forceinline__ void cp_wait(){
    asm volatile("cp.async.wait_group %0;" :: "n"(N));
}
// fp16 mma: D(f32) += A(f16)[16x16] * B(f16)[16x8 col-major]
__device__ __forceinline__ void mma16(float* c, const unsigned* a, const unsigned* b){
    asm volatile(
      "mma.sync.aligned.m16n8k16.row.col.f32.f16.f16.f32 "
      "{%0,%1,%2,%3},{%4,%5,%6,%7},{%8,%9},{%0,%1,%2,%3};"
      : "+f"(c[0]),"+f"(c[1]),"+f"(c[2]),"+f"(c[3])
      : "r"(a[0]),"r"(a[1]),"r"(a[2]),"r"(a[3]),"r"(b[0]),"r"(b[1]));
}
__device__ __forceinline__ void ldsm_x4(unsigned& r0, unsigned& r1, unsigned& r2, unsigned& r3,
                                        uint32_t addr){
    asm volatile("ldmatrix.sync.aligned.m8n8.x4.shared.b16 {%0,%1,%2,%3}, [%4];"
                 : "=r"(r0), "=r"(r1), "=r"(r2), "=r"(r3) : "r"(addr));
}

// ---------------------------------------------------------------- converts
__global__ __launch_bounds__(256) void convert_slots_kernel(const float* __restrict__ src){
    size_t i = ((size_t)blockIdx.x*256 + threadIdx.x) * 8;
    float4 a = *(const float4*)(src + i);
    float4 b = *(const float4*)(src + i + 4);
    __half2* d = (__half2*)(g_slots_h + i);
    d[0] = __floats2half2_rn(a.x, a.y);
    d[1] = __floats2half2_rn(a.z, a.w);
    d[2] = __floats2half2_rn(b.x, b.y);
    d[3] = __floats2half2_rn(b.z, b.w);
}

// g_wt_h[m][n][k] = (half)W_m[k][n]
__global__ __launch_bounds__(256) void transpose_w_kernel(
    const float* __restrict__ Wq, const float* __restrict__ Wk,
    const float* __restrict__ Wv, const float* __restrict__ Wo)
{
    __shared__ float tile[32][33];
    const float* W = (blockIdx.z==0)?Wq:((blockIdx.z==1)?Wk:((blockIdx.z==2)?Wv:Wo));
    __half* T = g_wt_h + (size_t)blockIdx.z * DD * DD;
    const int lane = threadIdx.x & 31, grp = threadIdx.x >> 5;
    const int x = blockIdx.x*32 + lane;
    const int y0 = blockIdx.y*32;
    #pragma unroll
    for (int i=0;i<4;i++){
        int yl = grp*4 + i;
        tile[yl][lane] = W[(size_t)(y0+yl)*DD + x];
    }
    __syncthreads();
    const int ncol = blockIdx.y*32 + lane;
    const int nrow0 = blockIdx.x*32;
    #pragma unroll
    for (int i=0;i<4;i++){
        int xl = grp*4 + i;
        T[(size_t)(nrow0+xl)*DD + ncol] = __float2half_rn(tile[lane][xl]);
    }
}

// ---------------------------------------------------------------- fp16 GEMM core (ldmatrix fragments)
__device__ __forceinline__ void gemm_core_h(
    const __half* __restrict__ A, const __half* __restrict__ Wt,
    const float* __restrict__ bias, const float* __restrict__ resid,
    float* __restrict__ Cf, __half* __restrict__ Ch, int mtile, int ntile)
{
    __shared__ __half As[2][128][16];
    __shared__ __half Bs[2][128][16];   // [n][k]
    const int tid = threadIdx.x;
    const __half* Ab = A  + (size_t)mtile * 128 * DD;
    const __half* Wb = Wt + (size_t)ntile * 128 * DD;
    const int r2 = tid >> 1, c2 = tid & 1;

    cpa16(&As[0][r2][c2*8], Ab + (size_t)r2*DD + c2*8);
    cpa16(&Bs[0][r2][c2*8], Wb + (size_t)r2*DD + c2*8);
    cp_commit();

    float acc[2][8][4];
    #pragma unroll
    for (int a=0;a<2;a++)
      #pragma unroll
      for (int b=0;b<8;b++)
        #pragma unroll
        for (int d=0;d<4;d++) acc[a][b][d]=0.f;

    const int wid = tid>>5, wm = wid>>1, wn = wid&1;
    const int lane = tid&31;

    // ldmatrix lane address tables (byte offsets within As[buf]/Bs[buf])
    const int i8 = lane & 7, qd = lane >> 3;
    uint32_t aOff[2], bOff[4];
    #pragma unroll
    for (int mt=0; mt<2; ++mt){
        int row = wm*32 + mt*16 + ((qd&1)?8:0) + i8;   // m0:r+0 c0, m1:r+8 c0, m2:r+0 c8, m3:r+8 c8
        int col = (qd>>1)?8:0;
        aOff[mt] = (uint32_t)(row*16 + col)*2;
    }
    #pragma unroll
    for (int p=0; p<4; ++p){
        int row = wn*64 + p*16 + ((qd>>1)?8:0) + i8;   // m0:n+0 c0, m1:n+0 c8, m2:n+8 c0, m3:n+8 c8
        int col = (qd&1)?8:0;
        bOff[p] = (uint32_t)(row*16 + col)*2;
    }
    const uint32_t aBase0 = (uint32_t)__cvta_generic_to_shared(&As[0][0][0]);
    const uint32_t aBase1 = (uint32_t)__cvta_generic_to_shared(&As[1][0][0]);
    const uint32_t bBase0 = (uint32_t)__cvta_generic_to_shared(&Bs[0][0][0]);
    const uint32_t bBase1 = (uint32_t)__cvta_generic_to_shared(&Bs[1][0][0]);

    for (int kt=0; kt<16; ++kt){
        if (kt < 15){
            const int buf = (kt+1)&1, k0 = (kt+1)*16;
            cpa16(&As[buf][r2][c2*8], Ab + (size_t)r2*DD + k0 + c2*8);
            cpa16(&Bs[buf][r2][c2*8], Wb + (size_t)r2*DD + k0 + c2*8);
            cp_commit();
            cp_wait<1>();
        } else {
            cp_wait<0>();
        }
        __syncthreads();
        const uint32_t aB = (kt&1) ? aBase1 : aBase0;
        const uint32_t bB = (kt&1) ? bBase1 : bBase0;
        unsigned afr[2][4], bfr[8][2];
        #pragma unroll
        for (int mt=0; mt<2; ++mt)
            ldsm_x4(afr[mt][0], afr[mt][1], afr[mt][2], afr[mt][3], aB + aOff[mt]);
        #pragma unroll
        for (int p=0; p<4; ++p)
            ldsm_x4(bfr[2*p][0], bfr[2*p][1], bfr[2*p+1][0], bfr[2*p+1][1], bB + bOff[p]);
        #pragma unroll
        for (int mt=0; mt<2; ++mt)
            #pragma unroll
            for (int nt=0; nt<8; ++nt)
                mma16(acc[mt][nt], afr[mt], bfr[nt]);
        __syncthreads();
    }

    const int g = lane>>2, tg = lane&3;
    #pragma unroll
    for (int mt=0; mt<2; ++mt){
        #pragma unroll
        for (int nt=0; nt<8; ++nt){
            const int col = ntile*128 + wn*64 + nt*8 + tg*2;
            const float2 bb = *(const float2*)(bias + col);
            const size_t r0 = (size_t)(mtile*128 + wm*32 + mt*16 + g);
            const size_t r1 = r0 + 8;
            float2 v0 = make_float2(acc[mt][nt][0]+bb.x, acc[mt][nt][1]+bb.y);
            float2 v1 = make_float2(acc[mt][nt][2]+bb.x, acc[mt][nt][3]+bb.y);
            if (Ch){
                *(__half2*)(Ch + r0*DD + col) = __floats2half2_rn(v0.x, v0.y);
                *(__half2*)(Ch + r1*DD + col) = __floats2half2_rn(v1.x, v1.y);
            } else {
                float2 s0 = *(const float2*)(resid + r0*DD + col);
                float2 s1 = *(const float2*)(resid + r1*DD + col);
                v0.x += s0.x; v0.y += s0.y; v1.x += s1.x; v1.y += s1.y;
                *(float2*)(Cf + r0*DD + col) = v0;
                *(float2*)(Cf + r1*DD + col) = v1;
            }
        }
    }
}

__global__ __launch_bounds__(256) void gemm_qkv_h_kernel(
    const float* __restrict__ bq, const float* __restrict__ bk,
    const float* __restrict__ bv)
{
    const int sel = blockIdx.x;
    const int which = sel>>1, ntile = sel&1, mtile = blockIdx.y;
    const __half* Wt = g_wt_h + (size_t)which * DD * DD;
    const float* b   = (which==0)?bq:((which==1)?bk:bv);
    __half* C        = (which==0)?g_qh:((which==1)?g_kh:g_vh);
    gemm_core_h(g_slots_h, Wt, b, nullptr, nullptr, C, mtile, ntile);
}

__global__ __launch_bounds__(256) void gemm_o_h_kernel(
    const float* __restrict__ bo, const float* __restrict__ slots,
    float* __restrict__ out)
{
    gemm_core_h(g_atth, g_wt_h + (size_t)3*DD*DD, bo, slots, out, nullptr,
                blockIdx.y, blockIdx.x);
}

// ---------------------------------------------------------------- attention (v2: half smem, conflict-free)
__global__ __launch_bounds__(256) void attn_kernel(
    const float* __restrict__ edge,
    const float* __restrict__ We1, const float* __restrict__ be1,
    const float* __restrict__ We2, const float* __restrict__ be2)
{
    __shared__ alignas(16) __half sQ[16*SHH];   // Q; reused as half out restage
    __shared__ alignas(16) __half sKh[16*SHH];
    __shared__ alignas(16) __half sV[16*SHH];
    __shared__ alignas(16) float sL[NH*16*16];
    __shared__ alignas(16) float sW1[NE*EHID];
    __shared__ alignas(16) float sW2[EHID*NH];
    __shared__ float sB1[EHID];
    __shared__ float sB2[NH];

    const int tid = threadIdx.x;
    const size_t b = blockIdx.x;
    const size_t base = b * (KS*DD);

    #pragma unroll
    for (int i=0;i<2;i++){
        int id = tid + 256*i;
        int r = id>>5, c8 = id&31;
        size_t goff = base + (size_t)r*DD + c8*8;
        uint4 vq = *(const uint4*)(g_qh + goff);
        uint4 vk = *(const uint4*)(g_kh + goff);
        uint4 vv = *(const uint4*)(g_vh + goff);
        uint2* dq = (uint2*)((char*)sQ  + r*520 + c8*16);
        uint2* dk = (uint2*)((char*)sKh + r*520 + c8*16);
        uint2* dv = (uint2*)((char*)sV  + r*520 + c8*16);
        dq[0] = make_uint2(vq.x, vq.y); dq[1] = make_uint2(vq.z, vq.w);
        dk[0] = make_uint2(vk.x, vk.y); dk[1] = make_uint2(vk.z, vk.w);
        dv[0] = make_uint2(vv.x, vv.y); dv[1] = make_uint2(vv.z, vv.w);
    }
    if (tid < 64) ((float4*)sW1)[tid] = ((const float4*)We1)[tid];
    if (tid < 32){ sB1[tid] = be1[tid]; ((float4*)sW2)[tid] = ((const float4*)We2)[tid]; }
    if (tid < 4)  sB2[tid] = be2[tid];
    __syncthreads();

    const int q = tid>>4, k = tid&15;

    #pragma unroll
    for (int h=0; h<NH; ++h){
        const uint2* qp = (const uint2*)((char*)sQ  + q*520 + h*128);
        const uint2* kp = (const uint2*)((char*)sKh + k*520 + h*128);
        float acc = 0.f;
        #pragma unroll
        for (int i=0;i<16;i++){
            uint2 ua = qp[i], ub = kp[i];
            float2 a0 = __half22float2(*(__half2*)&ua.x);
            float2 a1 = __half22float2(*(__half2*)&ua.y);
            float2 b0 = __half22float2(*(__half2*)&ub.x);
            float2 b1 = __half22float2(*(__half2*)&ub.y);
            acc += a0.x*b0.x + a0.y*b0.y + a1.x*b1.x + a1.y*b1.y;
        }
        sL[h*256 + q*16 + k] = acc * 0.125f;
    }

    {
        const float* ep = edge + ((b*KS + q)*KS + k)*NE;
        float e[8];
        *(float4*)&e[0] = *(const float4*)ep;
        *(float4*)&e[4] = *(const float4*)(ep+4);
        float oh[4] = {sB2[0], sB2[1], sB2[2], sB2[3]};
        #pragma unroll
        for (int j=0;j<EHID;++j){
            float hid = sB1[j];
            #pragma unroll
            for (int i=0;i<NE;++i) hid += e[i]*sW1[i*EHID + j];
            hid = fmaxf(hid, 0.f);
            #pragma unroll
            for (int h=0;h<NH;++h) oh[h] += hid * sW2[j*NH + h];
        }
        #pragma unroll
        for (int h=0;h<NH;++h) sL[h*256 + q*16 + k] += oh[h];
    }
    __syncthreads();

    if (tid < 64){
        const int h = tid>>4, qq = tid&15;
        float* row = &sL[h*256 + qq*16];
        float m = row[0];
        #pragma unroll
        for (int kk=1; kk<16; ++kk) m = fmaxf(m, row[kk]);
        float ex[16]; float s = 0.f;
        #pragma unroll
        for (int kk=0; kk<16; ++kk){ ex[kk] = expf(row[kk]-m); s += ex[kk]; }
        const float inv = 1.f / s;
        #pragma unroll
        for (int kk=0; kk<16; ++kk) row[kk] = ex[kk]*inv;
    }
    __syncthreads();

    const int c = tid & 15;
    float outv[NH][4];
    #pragma unroll
    for (int h=0; h<NH; ++h){
        float p[16];
        #pragma unroll
        for (int kk=0; kk<16; ++kk) p[kk] = sL[h*256 + q*16 + kk];
        float a0=0.f, a1=0.f, a2=0.f, a3=0.f;
        #pragma unroll
        for (int kk=0; kk<16; ++kk){
            uint2 uv = *(const uint2*)((char*)sV + kk*520 + (h*64 + 4*c)*2);
            float2 v01 = __half22float2(*(__half2*)&uv.x);
            float2 v23 = __half22float2(*(__half2*)&uv.y);
            a0 += p[kk]*v01.x; a1 += p[kk]*v01.y;
            a2 += p[kk]*v23.x; a3 += p[kk]*v23.y;
        }
        outv[h][0]=a0; outv[h][1]=a1; outv[h][2]=a2; outv[h][3]=a3;
    }
    #pragma unroll
    for (int h=0; h<NH; ++h){
        __half2 h01 = __floats2half2_rn(outv[h][0], outv[h][1]);
        __half2 h23 = __floats2half2_rn(outv[h][2], outv[h][3]);
        *(uint2*)((char*)sQ + q*520 + (h*64 + 4*c)*2) =
            make_uint2(*(unsigned*)&h01, *(unsigned*)&h23);
    }
    __syncthreads();
    {
        const int r = tid>>4, c0 = tid&15;
        const uint2* sp = (const uint2*)((char*)sQ + r*520 + c0*32);
        uint2 w0=sp[0], w1=sp[1], w2=sp[2], w3=sp[3];
        uint4 o0 = make_uint4(w0.x, w0.y, w1.x, w1.y);
        uint4 o1 = make_uint4(w2.x, w2.y, w3.x, w3.y);
        *(uint4*)(g_atth + base + (size_t)r*DD + c0*16)     = o0;
        *(uint4*)(g_atth + base + (size_t)r*DD + c0*16 + 8) = o1;
    }
}

// ---------------------------------------------------------------- LayerNorm (in-place)
__global__ __launch_bounds__(256) void ln_kernel(
    float* __restrict__ x, const float* __restrict__ gamma, const float* __restrict__ beta)
{
    const int row  = blockIdx.x*8 + (threadIdx.x>>5);
    const int lane = threadIdx.x & 31;
    float* xr = x + (size_t)row*DD + lane*8;
    float4 v0 = *(float4*)xr;
    float4 v1 = *(float4*)(xr+4);
    float s  = v0.x+v0.y+v0.z+v0.w + v1.x+v1.y+v1.z+v1.w;
    float ss = v0.x*v0.x+v0.y*v0.y+v0.z*v0.z+v0.w*v0.w
             + v1.x*v1.x+v1.y*v1.y+v1.z*v1.z+v1.w*v1.w;
    #pragma unroll
    for (int o=16;o>0;o>>=1){
        s  += __shfl_xor_sync(0xffffffffu, s,  o);
        ss += __shfl_xor_sync(0xffffffffu, ss, o);
    }
    const float mean = s * (1.f/256.f);
    const float var  = ss * (1.f/256.f) - mean*mean;
    const float rstd = rsqrtf(var + 1e-5f);
    const float4 g0 = *(const float4*)&gamma[lane*8];
    const float4 g1 = *(const float4*)&gamma[lane*8+4];
    const float4 b0 = *(const float4*)&beta[lane*8];
    const float4 b1 = *(const float4*)&beta[lane*8+4];
    v0.x = (v0.x-mean)*rstd*g0.x + b0.x;
    v0.y = (v0.y-mean)*rstd*g0.y + b0.y;
    v0.z = (v0.z-mean)*rstd*g0.z + b0.z;
    v0.w = (v0.w-mean)*rstd*g0.w + b0.w;
    v1.x = (v1.x-mean)*rstd*g1.x + b1.x;
    v1.y = (v1.y-mean)*rstd*g1.y + b1.y;
    v1.z = (v1.z-mean)*rstd*g1.z + b1.z;
    v1.w = (v1.w-mean)*rstd*g1.w + b1.w;
    *(float4*)xr     = v0;
    *(float4*)(xr+4) = v1;
}

// ---------------------------------------------------------------- launch
extern "C" void kernel_launch(void* const* d_in, const int* in_sizes, int n_in,
                              void* d_out, int out_size)
{
    const float* slots = (const float*)d_in[0];
    const float* edge  = (const float*)d_in[1];
    const float* Wq  = (const float*)d_in[2];
    const float* bq  = (const float*)d_in[3];
    const float* Wk  = (const float*)d_in[4];
    const float* bk  = (const float*)d_in[5];
    const float* Wv  = (const float*)d_in[6];
    const float* bv  = (const float*)d_in[7];
    const float* We1 = (const float*)d_in[8];
    const float* be1 = (const float*)d_in[9];
    const float* We2 = (const float*)d_in[10];
    const float* be2 = (const float*)d_in[11];
    const float* Wo  = (const float*)d_in[12];
    const float* bo  = (const float*)d_in[13];
    const float* gamma = (const float*)d_in[14];
    const float* beta  = (const float*)d_in[15];
    float* out = (float*)d_out;

    convert_slots_kernel<<<NROWS*DD/(256*8), 256>>>(slots);
    transpose_w_kernel<<<dim3(8,8,4), 256>>>(Wq, Wk, Wv, Wo);
    gemm_qkv_h_kernel<<<dim3(6,1024), 256>>>(bq, bk, bv);
    attn_kernel<<<NB, 256>>>(edge, We1, be1, We2, be2);
    gemm_o_h_kernel<<<dim3(2,1024), 256>>>(bo, slots, out);
    ln_kernel<<<NROWS/8, 256>>>(out, gamma, beta);
}